// round 7
// baseline (speedup 1.0000x reference)
#include <cuda_runtime.h>
#include <cuda_bf16.h>

// Problem: B=32, N=50000, K=32, E=6, F=3
//   f[b,n,f] = leaky_relu(x[b,n]*s[f] + g[n,f]),  s[f]=sum_e W[f,e], g[n,f]=W[f,:].emb[n,:]+bias[f]
//   out[n,k] = mask * mean_b exp(-||f[b,n,:]-f[b,nbr[n,k],:]||^2)          (2*theta = 1)
//
// Identities:
//   lrelu(u) = 0.6u + 0.4|u|; positively homogeneous => pre-scale s,g by
//   sqrt(log2 e) so sum(d^2) is log2-scaled and exp(-d) = ex2(-sum d^2)
//   with negation folded into FFMA modifiers. Scalar math (R3) — the f32x2
//   experiment moved work to the alu pipe and regressed.

#define NMAX 50000
#define BDIM 32
#define KDIM 32
#define C_SCALE 1.2011224087864498f   // sqrt(log2(e))

__device__ float  g_xT[NMAX * BDIM];   // 6.4 MB, transposed x
__device__ float4 g_g4[NMAX];          // 0.8 MB, pre-scaled g

// ---------------------------------------------------------------------------
// Kernel 1: transpose x (B,N) -> xT (N,B); compute scaled g4[n].
// ---------------------------------------------------------------------------
__global__ __launch_bounds__(256) void prep_kernel(
    const float* __restrict__ x,      // (B, N)
    const float* __restrict__ emb,    // (N, 6)
    const float* __restrict__ fcw,    // (3, 6)
    const float* __restrict__ fcb,    // (3,)
    int N)
{
    __shared__ float xt[32][33];
    const int n0 = blockIdx.x * 32;
    const int tx = threadIdx.x;
    const int ty = threadIdx.y;

    #pragma unroll
    for (int i = 0; i < 4; i++) {
        int b = ty + 8 * i;
        int n = n0 + tx;
        xt[b][tx] = (n < N) ? x[b * N + n] : 0.0f;
    }
    __syncthreads();

    #pragma unroll
    for (int i = 0; i < 4; i++) {
        int r = ty + 8 * i;
        int n = n0 + r;
        if (n < N) g_xT[n * BDIM + tx] = xt[tx][r];
    }

    const int tid = ty * 32 + tx;
    if (tid < 32) {
        int n = n0 + tid;
        if (n < N) {
            float e0 = emb[n * 6 + 0], e1 = emb[n * 6 + 1], e2 = emb[n * 6 + 2];
            float e3 = emb[n * 6 + 3], e4 = emb[n * 6 + 4], e5 = emb[n * 6 + 5];
            float g[3];
            #pragma unroll
            for (int f = 0; f < 3; f++) {
                g[f] = fcb[f]
                     + fcw[f * 6 + 0] * e0 + fcw[f * 6 + 1] * e1
                     + fcw[f * 6 + 2] * e2 + fcw[f * 6 + 3] * e3
                     + fcw[f * 6 + 4] * e4 + fcw[f * 6 + 5] * e5;
            }
            g_g4[n] = make_float4(C_SCALE * g[0], C_SCALE * g[1],
                                  C_SCALE * g[2], 0.0f);
        }
    }
}

// ---------------------------------------------------------------------------
// Kernel 2: one warp per node.
//   XOR-swizzled neighbor-x staging (no pad -> 32KB, 6 CTAs/SM):
//     element (k, b) lives at word  k*32 + (b ^ ((k&7)<<2)).
//     store (lane=b, loop k): banks lane ^ c, permutation        -> clean
//     read  (lane=k, float4 unit g^(lane&7)): distinct per phase -> clean
//   Phase 2: lane = k, scalar FFMA-imm math over b in float4 groups.
// ---------------------------------------------------------------------------
__global__ __launch_bounds__(256, 6) void pair_kernel(
    const int*  __restrict__ nl,      // (N, 32)
    const float* __restrict__ fcw,    // (3, 6)
    float* __restrict__ out,          // (N, 32)
    int N)
{
    __shared__ float4 xs4[8][KDIM * 8];                     // 32 KB
    __shared__ __align__(16) float fs0[8][32], fs1[8][32], fs2[8][32];

    const int wid  = threadIdx.x >> 5;
    const int lane = threadIdx.x & 31;
    const int n    = blockIdx.x * 8 + wid;
    if (n >= N) return;

    // scaled s[f] = C * sum_e W[f,e]
    float s0 = 0.f, s1 = 0.f, s2 = 0.f;
    #pragma unroll
    for (int e = 0; e < 6; e++) {
        s0 += fcw[e];
        s1 += fcw[6 + e];
        s2 += fcw[12 + e];
    }
    s0 *= C_SCALE; s1 *= C_SCALE; s2 *= C_SCALE;

    // --- Phase 1: lane = b : self f (SoA) ---
    {
        float  xv = g_xT[n * BDIM + lane];
        float4 gs = g_g4[n];
        float u0 = fmaf(xv, s0, gs.x);
        float u1 = fmaf(xv, s1, gs.y);
        float u2 = fmaf(xv, s2, gs.z);
        fs0[wid][lane] = fmaf(0.4f, fabsf(u0), 0.6f * u0);
        fs1[wid][lane] = fmaf(0.4f, fabsf(u1), 0.6f * u1);
        fs2[wid][lane] = fmaf(0.4f, fabsf(u2), 0.6f * u2);
    }

    const int   j    = nl[n * KDIM + lane];
    const int   jc   = (j < 0) ? 0 : j;
    const float mask = (j < 0) ? 0.0f : 1.0f;
    const float4 gj  = g_g4[jc];

    // Stage neighbor x rows, swizzled.
    float* xs = (float*)xs4[wid];
    #pragma unroll 4
    for (int k = 0; k < KDIM; k++) {
        int jj = __shfl_sync(0xffffffffu, jc, k);
        xs[k * 32 + (lane ^ ((k & 7) << 2))] = g_xT[jj * BDIM + lane];
    }
    __syncwarp();

    // --- Phase 2: lane = k ---
    const float4* xrow = xs4[wid] + lane * 8;
    const int     sw   = lane & 7;
    float acc0 = 0.0f, acc1 = 0.0f;

    #pragma unroll
    for (int g = 0; g < 8; g++) {
        float4 xv4 = xrow[g ^ sw];                     // b = 4g .. 4g+3
        float4 f0v = *(const float4*)&fs0[wid][g * 4];
        float4 f1v = *(const float4*)&fs1[wid][g * 4];
        float4 f2v = *(const float4*)&fs2[wid][g * 4];

        #define PAIR_STEP(XV, F0, F1, F2, ACC)                                \
        {                                                                     \
            float u0 = fmaf((XV), s0, gj.x);                                  \
            float u1 = fmaf((XV), s1, gj.y);                                  \
            float u2 = fmaf((XV), s2, gj.z);                                  \
            float d0 = fmaf(u0, -0.6f, (F0)); d0 = fmaf(fabsf(u0), -0.4f, d0);\
            float d1 = fmaf(u1, -0.6f, (F1)); d1 = fmaf(fabsf(u1), -0.4f, d1);\
            float d2 = fmaf(u2, -0.6f, (F2)); d2 = fmaf(fabsf(u2), -0.4f, d2);\
            float dn = -d0 * d0;                                              \
            dn = fmaf(d1, -d1, dn);                                           \
            dn = fmaf(d2, -d2, dn);                                           \
            float ex;                                                         \
            asm("ex2.approx.ftz.f32 %0, %1;" : "=f"(ex) : "f"(dn));           \
            (ACC) += ex;                                                      \
        }

        PAIR_STEP(xv4.x, f0v.x, f1v.x, f2v.x, acc0)
        PAIR_STEP(xv4.y, f0v.y, f1v.y, f2v.y, acc1)
        PAIR_STEP(xv4.z, f0v.z, f1v.z, f2v.z, acc0)
        PAIR_STEP(xv4.w, f0v.w, f1v.w, f2v.w, acc1)
        #undef PAIR_STEP
    }

    out[n * KDIM + lane] = (acc0 + acc1) * (1.0f / 32.0f) * mask;
}

// ---------------------------------------------------------------------------
extern "C" void kernel_launch(void* const* d_in, const int* in_sizes, int n_in,
                              void* d_out, int out_size)
{
    const float* x    = (const float*)d_in[0];   // (B, N)
    const float* emb  = (const float*)d_in[1];   // (N, 6)
    const float* fcw  = (const float*)d_in[2];   // (3, 6)
    const float* fcb  = (const float*)d_in[3];   // (3,)
    const int*   nl   = (const int*)d_in[4];     // (N, 32)
    float*       out  = (float*)d_out;           // (N, 32)

    const int N = in_sizes[1] / 6;               // 50000

    dim3 b1(32, 8);
    prep_kernel<<<(N + 31) / 32, b1>>>(x, emb, fcw, fcb, N);

    pair_kernel<<<(N + 7) / 8, 256>>>(nl, fcw, out, N);
}

// round 10
// speedup vs baseline: 1.2363x; 1.2363x over previous
#include <cuda_runtime.h>
#include <cuda_bf16.h>

// Problem: B=32, N=50000, K=32, E=6, F=3
//   f[b,n,f] = leaky_relu(x[b,n]*s[f] + g[n,f]),  s[f]=sum_e W[f,e], g[n,f]=W[f,:].emb[n,:]+bias[f]
//   out[n,k] = mask * mean_b exp(-||f[b,n,:]-f[b,nbr[n,k],:]||^2)          (2*theta = 1)
//
// Identities:
//   lrelu(u) = 0.6u + 0.4|u|; positively homogeneous => pre-scale s,g by
//   sqrt(log2 e) so sum(d^2) is log2-scaled and exp(-d) = ex2(-sum d^2)
//   with negation folded into FFMA modifiers.
// Layout lesson (R6): padded XPAD=36 layout with compile-time-immediate LDS
//   offsets; XOR swizzle / tight reg caps inflate the alu pipe. This round:
//   R3 kernel exactly, but 128-thread CTAs so smem/regs allow 11 CTAs/SM.

#define NMAX 50000
#define BDIM 32
#define KDIM 32
#define XPAD 36                       // (36w mod 32) = 4-word step: LDS.128 conflict-free
#define C_SCALE 1.2011224087864498f   // sqrt(log2(e))
#define PWARPS 4                      // warps per pair_kernel CTA

__device__ float  g_xT[NMAX * BDIM];   // 6.4 MB, transposed x
__device__ float4 g_g4[NMAX];          // 0.8 MB, pre-scaled g

// ---------------------------------------------------------------------------
// Kernel 1: transpose x (B,N) -> xT (N,B); compute scaled g4[n].
// ---------------------------------------------------------------------------
__global__ __launch_bounds__(256) void prep_kernel(
    const float* __restrict__ x,      // (B, N)
    const float* __restrict__ emb,    // (N, 6)
    const float* __restrict__ fcw,    // (3, 6)
    const float* __restrict__ fcb,    // (3,)
    int N)
{
    __shared__ float xt[32][33];
    const int n0 = blockIdx.x * 32;
    const int tx = threadIdx.x;
    const int ty = threadIdx.y;

    #pragma unroll
    for (int i = 0; i < 4; i++) {
        int b = ty + 8 * i;
        int n = n0 + tx;
        xt[b][tx] = (n < N) ? x[b * N + n] : 0.0f;
    }
    __syncthreads();

    #pragma unroll
    for (int i = 0; i < 4; i++) {
        int r = ty + 8 * i;
        int n = n0 + r;
        if (n < N) g_xT[n * BDIM + tx] = xt[tx][r];
    }

    const int tid = ty * 32 + tx;
    if (tid < 32) {
        int n = n0 + tid;
        if (n < N) {
            float e0 = emb[n * 6 + 0], e1 = emb[n * 6 + 1], e2 = emb[n * 6 + 2];
            float e3 = emb[n * 6 + 3], e4 = emb[n * 6 + 4], e5 = emb[n * 6 + 5];
            float g[3];
            #pragma unroll
            for (int f = 0; f < 3; f++) {
                g[f] = fcb[f]
                     + fcw[f * 6 + 0] * e0 + fcw[f * 6 + 1] * e1
                     + fcw[f * 6 + 2] * e2 + fcw[f * 6 + 3] * e3
                     + fcw[f * 6 + 4] * e4 + fcw[f * 6 + 5] * e5;
            }
            g_g4[n] = make_float4(C_SCALE * g[0], C_SCALE * g[1],
                                  C_SCALE * g[2], 0.0f);
        }
    }
}

// ---------------------------------------------------------------------------
// Kernel 2: one warp per node, 4 warps per CTA (smem/CTA ~20KB -> 11 CTAs/SM).
//   Phase 1 (lane = b): stage neighbor x-rows as xs[k][b] (pad 36), self-f SoA.
//   Phase 2 (lane = k): loop b in float4 groups, immediate-offset LDS,
//     FFMA-imm leaky-relu distances, bare ex2.approx.
// ---------------------------------------------------------------------------
__global__ __launch_bounds__(32 * PWARPS, 11) void pair_kernel(
    const int*  __restrict__ nl,      // (N, 32)
    const float* __restrict__ fcw,    // (3, 6)
    float* __restrict__ out,          // (N, 32)
    int N)
{
    __shared__ float xs[PWARPS][KDIM * XPAD];
    __shared__ __align__(16) float fs0[PWARPS][32], fs1[PWARPS][32], fs2[PWARPS][32];

    const int wid  = threadIdx.x >> 5;
    const int lane = threadIdx.x & 31;
    const int n    = blockIdx.x * PWARPS + wid;
    if (n >= N) return;

    // scaled s[f] = C * sum_e W[f,e]
    float s0 = 0.f, s1 = 0.f, s2 = 0.f;
    #pragma unroll
    for (int e = 0; e < 6; e++) {
        s0 += fcw[e];
        s1 += fcw[6 + e];
        s2 += fcw[12 + e];
    }
    s0 *= C_SCALE; s1 *= C_SCALE; s2 *= C_SCALE;

    // --- Phase 1: lane = b : self f (SoA) ---
    {
        float  xv = g_xT[n * BDIM + lane];
        float4 gs = g_g4[n];
        float u0 = fmaf(xv, s0, gs.x);
        float u1 = fmaf(xv, s1, gs.y);
        float u2 = fmaf(xv, s2, gs.z);
        fs0[wid][lane] = fmaf(0.4f, fabsf(u0), 0.6f * u0);
        fs1[wid][lane] = fmaf(0.4f, fabsf(u1), 0.6f * u1);
        fs2[wid][lane] = fmaf(0.4f, fabsf(u2), 0.6f * u2);
    }

    const int   j    = nl[n * KDIM + lane];
    const int   jc   = (j < 0) ? 0 : j;
    const float mask = (j < 0) ? 0.0f : 1.0f;
    const float4 gj  = g_g4[jc];

    // Stage neighbor x rows: xs[k][b = lane]. Store banks (4k+lane)%32: clean.
    #pragma unroll 4
    for (int k = 0; k < KDIM; k++) {
        int jj = __shfl_sync(0xffffffffu, jc, k);
        xs[wid][k * XPAD + lane] = g_xT[jj * BDIM + lane];
    }
    __syncwarp();

    // --- Phase 2: lane = k ---
    const float* xrow = &xs[wid][lane * XPAD];
    float acc0 = 0.0f, acc1 = 0.0f;

    #pragma unroll
    for (int g = 0; g < 8; g++) {
        float4 xv4  = *(const float4*)(xrow + g * 4);
        float4 f0v  = *(const float4*)&fs0[wid][g * 4];
        float4 f1v  = *(const float4*)&fs1[wid][g * 4];
        float4 f2v  = *(const float4*)&fs2[wid][g * 4];

        #define PAIR_STEP(XV, F0, F1, F2, ACC)                                \
        {                                                                     \
            float u0 = fmaf((XV), s0, gj.x);                                  \
            float u1 = fmaf((XV), s1, gj.y);                                  \
            float u2 = fmaf((XV), s2, gj.z);                                  \
            float d0 = fmaf(u0, -0.6f, (F0)); d0 = fmaf(fabsf(u0), -0.4f, d0);\
            float d1 = fmaf(u1, -0.6f, (F1)); d1 = fmaf(fabsf(u1), -0.4f, d1);\
            float d2 = fmaf(u2, -0.6f, (F2)); d2 = fmaf(fabsf(u2), -0.4f, d2);\
            float dn = -d0 * d0;                                              \
            dn = fmaf(d1, -d1, dn);                                           \
            dn = fmaf(d2, -d2, dn);                                           \
            float ex;                                                         \
            asm("ex2.approx.ftz.f32 %0, %1;" : "=f"(ex) : "f"(dn));           \
            (ACC) += ex;                                                      \
        }

        PAIR_STEP(xv4.x, f0v.x, f1v.x, f2v.x, acc0)
        PAIR_STEP(xv4.y, f0v.y, f1v.y, f2v.y, acc1)
        PAIR_STEP(xv4.z, f0v.z, f1v.z, f2v.z, acc0)
        PAIR_STEP(xv4.w, f0v.w, f1v.w, f2v.w, acc1)
        #undef PAIR_STEP
    }

    out[n * KDIM + lane] = (acc0 + acc1) * (1.0f / 32.0f) * mask;
}

// ---------------------------------------------------------------------------
extern "C" void kernel_launch(void* const* d_in, const int* in_sizes, int n_in,
                              void* d_out, int out_size)
{
    const float* x    = (const float*)d_in[0];   // (B, N)
    const float* emb  = (const float*)d_in[1];   // (N, 6)
    const float* fcw  = (const float*)d_in[2];   // (3, 6)
    const float* fcb  = (const float*)d_in[3];   // (3,)
    const int*   nl   = (const int*)d_in[4];     // (N, 32)
    float*       out  = (float*)d_out;           // (N, 32)

    const int N = in_sizes[1] / 6;               // 50000

    dim3 b1(32, 8);
    prep_kernel<<<(N + 31) / 32, b1>>>(x, emb, fcw, fcb, N);

    pair_kernel<<<(N + PWARPS - 1) / PWARPS, 32 * PWARPS>>>(nl, fcw, out, N);
}

// round 14
// speedup vs baseline: 1.3968x; 1.1298x over previous
#include <cuda_runtime.h>
#include <cuda_bf16.h>

// Problem: B=32, N=50000, K=32, E=6, F=3
//   f[b,n,f] = leaky_relu(x[b,n]*s[f] + g[n,f]),  s[f]=sum_e W[f,e], g[n,f]=W[f,:].emb[n,:]+bias[f]
//   out[n,k] = mask * mean_b exp(-||f[b,n,:]-f[b,nbr[n,k],:]||^2)          (2*theta = 1)
//
// Identities:
//   lrelu(u) = 0.6u + 0.4|u|; positively homogeneous => pre-scale s,g by
//   sqrt(log2 e) so sum(d^2) is log2-scaled and exp(-d) = ex2(-sum d^2)
//   with negation folded into FFMA modifiers.
// Frozen lessons: XPAD=36 immediate-offset LDS layout (R6: XOR swizzle bloats
//   alu pipe); scalar math (R4: f32x2 packing bloats alu pipe); 128-thr CTAs.
// R11 fix: staging needs 8 lanes per row (8 float4s = full 32-float row),
//   4 rows per iteration, 8 iterations. R11's 4-lane split left half of each
//   row unwritten (rel_err 0.17).

#define NMAX 50000
#define BDIM 32
#define KDIM 32
#define XPAD 36                       // (36w mod 32) = 4-word step: LDS.128 conflict-free
#define C_SCALE 1.2011224087864498f   // sqrt(log2(e))
#define PWARPS 4                      // warps per pair_kernel CTA

__device__ __align__(16) float  g_xT[NMAX * BDIM];   // 6.4 MB, transposed x
__device__ float4 g_g4[NMAX];                        // 0.8 MB, pre-scaled g

// ---------------------------------------------------------------------------
// Kernel 1: transpose x (B,N) -> xT (N,B); compute scaled g4[n].
// ---------------------------------------------------------------------------
__global__ __launch_bounds__(256) void prep_kernel(
    const float* __restrict__ x,      // (B, N)
    const float* __restrict__ emb,    // (N, 6)
    const float* __restrict__ fcw,    // (3, 6)
    const float* __restrict__ fcb,    // (3,)
    int N)
{
    __shared__ float xt[32][33];
    const int n0 = blockIdx.x * 32;
    const int tx = threadIdx.x;
    const int ty = threadIdx.y;

    #pragma unroll
    for (int i = 0; i < 4; i++) {
        int b = ty + 8 * i;
        int n = n0 + tx;
        xt[b][tx] = (n < N) ? x[b * N + n] : 0.0f;
    }
    __syncthreads();

    #pragma unroll
    for (int i = 0; i < 4; i++) {
        int r = ty + 8 * i;
        int n = n0 + r;
        if (n < N) g_xT[n * BDIM + tx] = xt[tx][r];
    }

    const int tid = ty * 32 + tx;
    if (tid < 32) {
        int n = n0 + tid;
        if (n < N) {
            float e0 = emb[n * 6 + 0], e1 = emb[n * 6 + 1], e2 = emb[n * 6 + 2];
            float e3 = emb[n * 6 + 3], e4 = emb[n * 6 + 4], e5 = emb[n * 6 + 5];
            float g[3];
            #pragma unroll
            for (int f = 0; f < 3; f++) {
                g[f] = fcb[f]
                     + fcw[f * 6 + 0] * e0 + fcw[f * 6 + 1] * e1
                     + fcw[f * 6 + 2] * e2 + fcw[f * 6 + 3] * e3
                     + fcw[f * 6 + 4] * e4 + fcw[f * 6 + 5] * e5;
            }
            g_g4[n] = make_float4(C_SCALE * g[0], C_SCALE * g[1],
                                  C_SCALE * g[2], 0.0f);
        }
    }
}

// ---------------------------------------------------------------------------
// Kernel 2: one warp per node, 4 warps per CTA (~20KB smem -> 11 CTAs/SM).
//   Staging: 8 lanes per neighbor row (one float4 each = full 128B row),
//     4 rows per iteration, 8 iterations; LDG.128 + STS.128 into xs (pad 36).
//   Phase 2 (lane = k): float4 groups over b, immediate-offset LDS,
//     FFMA-imm leaky-relu distances, bare ex2.approx.
// ---------------------------------------------------------------------------
__global__ __launch_bounds__(32 * PWARPS, 11) void pair_kernel(
    const int*  __restrict__ nl,      // (N, 32)
    const float* __restrict__ fcw,    // (3, 6)
    float* __restrict__ out,          // (N, 32)
    int N)
{
    __shared__ __align__(16) float xs[PWARPS][KDIM * XPAD];
    __shared__ __align__(16) float fs0[PWARPS][32], fs1[PWARPS][32], fs2[PWARPS][32];

    const int wid  = threadIdx.x >> 5;
    const int lane = threadIdx.x & 31;
    const int n    = blockIdx.x * PWARPS + wid;
    if (n >= N) return;

    // scaled s[f] = C * sum_e W[f,e]
    float s0 = 0.f, s1 = 0.f, s2 = 0.f;
    #pragma unroll
    for (int e = 0; e < 6; e++) {
        s0 += fcw[e];
        s1 += fcw[6 + e];
        s2 += fcw[12 + e];
    }
    s0 *= C_SCALE; s1 *= C_SCALE; s2 *= C_SCALE;

    // --- Phase 1: lane = b : self f (SoA) ---
    {
        float  xv = g_xT[n * BDIM + lane];
        float4 gs = g_g4[n];
        float u0 = fmaf(xv, s0, gs.x);
        float u1 = fmaf(xv, s1, gs.y);
        float u2 = fmaf(xv, s2, gs.z);
        fs0[wid][lane] = fmaf(0.4f, fabsf(u0), 0.6f * u0);
        fs1[wid][lane] = fmaf(0.4f, fabsf(u1), 0.6f * u1);
        fs2[wid][lane] = fmaf(0.4f, fabsf(u2), 0.6f * u2);
    }

    const int   j    = nl[n * KDIM + lane];
    const int   jc   = (j < 0) ? 0 : j;
    const float mask = (j < 0) ? 0.0f : 1.0f;
    const float4 gj  = g_g4[jc];

    // Vectorized staging: 8 lanes per row (full 128B row = 8 float4s),
    // 4 rows per iteration, 8 iterations for all 32 rows.
    {
        const float4* xT4 = (const float4*)g_xT;      // node row = 8 float4s
        const int c = lane & 7;                       // float4 index in row
        const int r = lane >> 3;                      // row-within-group 0..3
        #pragma unroll
        for (int i = 0; i < 8; i++) {
            int k  = 4 * i + r;                       // destination row
            int jj = __shfl_sync(0xffffffffu, jc, k); // that row's neighbor
            float4 v = xT4[jj * 8 + c];
            *(float4*)&xs[wid][k * XPAD + 4 * c] = v;
        }
    }
    __syncwarp();

    // --- Phase 2: lane = k ---
    const float* xrow = &xs[wid][lane * XPAD];
    float acc0 = 0.0f, acc1 = 0.0f;

    #pragma unroll
    for (int g = 0; g < 8; g++) {
        float4 xv4  = *(const float4*)(xrow + g * 4);
        float4 f0v  = *(const float4*)&fs0[wid][g * 4];
        float4 f1v  = *(const float4*)&fs1[wid][g * 4];
        float4 f2v  = *(const float4*)&fs2[wid][g * 4];

        #define PAIR_STEP(XV, F0, F1, F2, ACC)                                \
        {                                                                     \
            float u0 = fmaf((XV), s0, gj.x);                                  \
            float u1 = fmaf((XV), s1, gj.y);                                  \
            float u2 = fmaf((XV), s2, gj.z);                                  \
            float d0 = fmaf(u0, -0.6f, (F0)); d0 = fmaf(fabsf(u0), -0.4f, d0);\
            float d1 = fmaf(u1, -0.6f, (F1)); d1 = fmaf(fabsf(u1), -0.4f, d1);\
            float d2 = fmaf(u2, -0.6f, (F2)); d2 = fmaf(fabsf(u2), -0.4f, d2);\
            float dn = -d0 * d0;                                              \
            dn = fmaf(d1, -d1, dn);                                           \
            dn = fmaf(d2, -d2, dn);                                           \
            float ex;                                                         \
            asm("ex2.approx.ftz.f32 %0, %1;" : "=f"(ex) : "f"(dn));           \
            (ACC) += ex;                                                      \
        }

        PAIR_STEP(xv4.x, f0v.x, f1v.x, f2v.x, acc0)
        PAIR_STEP(xv4.y, f0v.y, f1v.y, f2v.y, acc1)
        PAIR_STEP(xv4.z, f0v.z, f1v.z, f2v.z, acc0)
        PAIR_STEP(xv4.w, f0v.w, f1v.w, f2v.w, acc1)
        #undef PAIR_STEP
    }

    out[n * KDIM + lane] = (acc0 + acc1) * (1.0f / 32.0f) * mask;
}

// ---------------------------------------------------------------------------
extern "C" void kernel_launch(void* const* d_in, const int* in_sizes, int n_in,
                              void* d_out, int out_size)
{
    const float* x    = (const float*)d_in[0];   // (B, N)
    const float* emb  = (const float*)d_in[1];   // (N, 6)
    const float* fcw  = (const float*)d_in[2];   // (3, 6)
    const float* fcb  = (const float*)d_in[3];   // (3,)
    const int*   nl   = (const int*)d_in[4];     // (N, 32)
    float*       out  = (float*)d_out;           // (N, 32)

    const int N = in_sizes[1] / 6;               // 50000

    dim3 b1(32, 8);
    prep_kernel<<<(N + 31) / 32, b1>>>(x, emb, fcw, fcb, N);

    pair_kernel<<<(N + PWARPS - 1) / PWARPS, 32 * PWARPS>>>(nl, fcw, out, N);
}